// round 11
// baseline (speedup 1.0000x reference)
#include <cuda_runtime.h>
#include <cuda_bf16.h>
#include <cstdint>

#define NN 100000
#define EE 1600000
#define FF 128
#define RR 50
#define BN_EPS 1e-3f

// Scratch (allocation-free rule: device globals)
__device__ float g_h[(size_t)NN * FF];    // batchnormed features
__device__ float g_pre[(size_t)NN * FF];  // coeff-residual + aggregated messages
__device__ int   g_deg[NN];               // per-row edge count
__device__ int   g_rowptr[NN + 1];        // CSR row pointers
__device__ int   g_cursor[NN];            // fill cursors
__device__ int2  g_cpack[EE];             // packed (col, w_bits) per CSR slot
__device__ int   g_blocksum[64];          // scan partials
__device__ int   g_ticket;                // spmm work dispenser

// ---------------------------------------------------------------------------
// Kernel 0: zero g_deg + reset spmm ticket
// ---------------------------------------------------------------------------
__global__ void zero_deg_kernel()
{
    int i = blockIdx.x * blockDim.x + threadIdx.x;
    if (i < NN) g_deg[i] = 0;
    if (i == 0) g_ticket = 0;
}

// ---------------------------------------------------------------------------
// Kernel 1: BatchNorm (inference) into g_h.
// ---------------------------------------------------------------------------
__global__ void __launch_bounds__(256)
bn_kernel(const float* __restrict__ x,
          const float* __restrict__ gamma,
          const float* __restrict__ beta,
          const float* __restrict__ mean,
          const float* __restrict__ var)
{
    __shared__ float s_scale[FF], s_shift[FF];
    int tid = threadIdx.x;
    if (tid < FF) {
        float sc = gamma[tid] * rsqrtf(var[tid] + BN_EPS);
        s_scale[tid] = sc;
        s_shift[tid] = beta[tid] - mean[tid] * sc;
    }
    __syncthreads();

    int idx = blockIdx.x * blockDim.x + tid;
    if (idx >= NN * (FF / 4)) return;

    int c = (idx & 31) * 4;
    float4 xv = ((const float4*)x)[idx];
    float4 hv;
    hv.x = xv.x * s_scale[c + 0] + s_shift[c + 0];
    hv.y = xv.y * s_scale[c + 1] + s_shift[c + 1];
    hv.z = xv.z * s_scale[c + 2] + s_shift[c + 2];
    hv.w = xv.w * s_scale[c + 3] + s_shift[c + 3];
    ((float4*)g_h)[idx] = hv;
}

// ---------------------------------------------------------------------------
// Kernel 2: degree histogram
// ---------------------------------------------------------------------------
__global__ void hist_kernel(const int* __restrict__ rows)
{
    int e = blockIdx.x * blockDim.x + threadIdx.x;
    if (e < EE) atomicAdd(&g_deg[rows[e]], 1);
}

// ---------------------------------------------------------------------------
// Kernel 3a: block-local exclusive scan. 25 blocks x 256 thr x 16 elems.
// ---------------------------------------------------------------------------
#define SCB 4096
#define SCAN_BLOCKS ((NN + SCB - 1) / SCB)   // 25

__global__ void __launch_bounds__(256)
scan_blocks_kernel()
{
    __shared__ int sh[SCB];
    __shared__ int warpsums[8];
    int b = blockIdx.x, t = threadIdx.x;
    int base = b * SCB;

#pragma unroll
    for (int i = 0; i < 16; i++) {
        int idx = base + i * 256 + t;
        sh[i * 256 + t] = (idx < NN) ? g_deg[idx] : 0;
    }
    __syncthreads();

    int o = t * 16;
    int my = 0;
#pragma unroll
    for (int i = 0; i < 16; i++) my += sh[o + i];

    int lane = t & 31, wid = t >> 5;
    int pref = my;
#pragma unroll
    for (int d = 1; d < 32; d <<= 1) {
        int v = __shfl_up_sync(0xffffffffu, pref, d);
        if (lane >= d) pref += v;
    }
    if (lane == 31) warpsums[wid] = pref;
    __syncthreads();

    int woff = 0;
#pragma unroll
    for (int i = 0; i < 8; i++)
        if (i < wid) woff += warpsums[i];

    int run = woff + pref - my;
#pragma unroll
    for (int i = 0; i < 16; i++) {
        int v = sh[o + i];
        sh[o + i] = run;
        run += v;
    }
    if (t == 255) g_blocksum[b] = run;
    __syncthreads();

#pragma unroll
    for (int i = 0; i < 16; i++) {
        int idx = base + i * 256 + t;
        if (idx < NN) g_rowptr[idx] = sh[i * 256 + t];
    }
}

// ---------------------------------------------------------------------------
// Kernel 3b: add block offsets; init cursors; set rowptr[NN].
// ---------------------------------------------------------------------------
__global__ void __launch_bounds__(256)
scan_addoff_kernel()
{
    __shared__ int soff[32];
    int t = threadIdx.x;
    if (t < 32) {
        int v = (t < SCAN_BLOCKS) ? g_blocksum[t] : 0;
        int p = v;
#pragma unroll
        for (int d = 1; d < 32; d <<= 1) {
            int u = __shfl_up_sync(0xffffffffu, p, d);
            if (t >= d) p += u;
        }
        soff[t] = p - v;     // exclusive
    }
    __syncthreads();

    int i = blockIdx.x * blockDim.x + t;
    if (i < NN) {
        int v = g_rowptr[i] + soff[i >> 12];   // SCB == 4096
        g_rowptr[i] = v;
        g_cursor[i] = v;
    }
    if (i == 0) g_rowptr[NN] = EE;
}

// ---------------------------------------------------------------------------
// Kernel 4: fill CSR slots with (col, precomputed weight)
// ---------------------------------------------------------------------------
__global__ void fill_kernel(const int*   __restrict__ rows,
                            const int*   __restrict__ cols,
                            const float* __restrict__ vals,
                            const int*   __restrict__ rels,
                            const float* __restrict__ rc)
{
    int e = blockIdx.x * blockDim.x + threadIdx.x;
    if (e >= EE) return;
    int r = rows[e];
    float w = vals[e] / (rc[rels[e]] + 1.0f);
    int pos = atomicAdd(&g_cursor[r], 1);
    int2 p;
    p.x = cols[e];
    p.y = __float_as_int(w);
    g_cpack[pos] = p;
}

// ---------------------------------------------------------------------------
// Kernel 5: SpMM-CSR, persistent warps, 8-node ticket chunks (load balance),
// register accumulation, coeff residual fused, 8-wide edge unroll.
// ---------------------------------------------------------------------------
#define SPMM_CHUNK 8

__global__ void __launch_bounds__(256)
spmm_csr_kernel(const float* __restrict__ coeff)
{
    int lane = threadIdx.x & 31;

    for (;;) {
        int base = 0;
        if (lane == 0) base = atomicAdd(&g_ticket, SPMM_CHUNK);
        base = __shfl_sync(0xffffffffu, base, 0);
        if (base >= NN) break;
        int lim = min(base + SPMM_CHUNK, NN);

        for (int node = base; node < lim; node++) {
            float4 hv = __ldg(((const float4*)(g_h + (size_t)node * FF)) + lane);
            float cm = coeff[node] + 1.0f;
            float ax = hv.x * cm, ay = hv.y * cm, az = hv.z * cm, aw = hv.w * cm;

            int p   = g_rowptr[node];
            int end = g_rowptr[node + 1];

            for (; p + 8 <= end; p += 8) {
                int2 e0 = g_cpack[p + 0], e1 = g_cpack[p + 1];
                int2 e2 = g_cpack[p + 2], e3 = g_cpack[p + 3];
                int2 e4 = g_cpack[p + 4], e5 = g_cpack[p + 5];
                int2 e6 = g_cpack[p + 6], e7 = g_cpack[p + 7];
                float4 h0 = __ldg(((const float4*)(g_h + (size_t)e0.x * FF)) + lane);
                float4 h1 = __ldg(((const float4*)(g_h + (size_t)e1.x * FF)) + lane);
                float4 h2 = __ldg(((const float4*)(g_h + (size_t)e2.x * FF)) + lane);
                float4 h3 = __ldg(((const float4*)(g_h + (size_t)e3.x * FF)) + lane);
                float4 h4 = __ldg(((const float4*)(g_h + (size_t)e4.x * FF)) + lane);
                float4 h5 = __ldg(((const float4*)(g_h + (size_t)e5.x * FF)) + lane);
                float4 h6 = __ldg(((const float4*)(g_h + (size_t)e6.x * FF)) + lane);
                float4 h7 = __ldg(((const float4*)(g_h + (size_t)e7.x * FF)) + lane);
                float w0 = __int_as_float(e0.y), w1 = __int_as_float(e1.y);
                float w2 = __int_as_float(e2.y), w3 = __int_as_float(e3.y);
                float w4 = __int_as_float(e4.y), w5 = __int_as_float(e5.y);
                float w6 = __int_as_float(e6.y), w7 = __int_as_float(e7.y);
                ax += w0*h0.x + w1*h1.x + w2*h2.x + w3*h3.x + w4*h4.x + w5*h5.x + w6*h6.x + w7*h7.x;
                ay += w0*h0.y + w1*h1.y + w2*h2.y + w3*h3.y + w4*h4.y + w5*h5.y + w6*h6.y + w7*h7.y;
                az += w0*h0.z + w1*h1.z + w2*h2.z + w3*h3.z + w4*h4.z + w5*h5.z + w6*h6.z + w7*h7.z;
                aw += w0*h0.w + w1*h1.w + w2*h2.w + w3*h3.w + w4*h4.w + w5*h5.w + w6*h6.w + w7*h7.w;
            }
            for (; p < end; p++) {
                int2 e0 = g_cpack[p];
                float4 h0 = __ldg(((const float4*)(g_h + (size_t)e0.x * FF)) + lane);
                float w0 = __int_as_float(e0.y);
                ax += w0 * h0.x; ay += w0 * h0.y; az += w0 * h0.z; aw += w0 * h0.w;
            }

            ((float4*)(g_pre + (size_t)node * FF))[lane] = make_float4(ax, ay, az, aw);
        }
    }
}

// ---------------------------------------------------------------------------
// Kernel 6: out = pre @ W + bias, packed-f32x2 FFMA, 128-row tile.
// k unrolled by 4 with float4 A-loads over k (8 LDS.128 replace 32 LDS.32).
// ---------------------------------------------------------------------------
#define AS_STRIDE 132

__global__ void __launch_bounds__(256)
gemm_kernel(const float* __restrict__ W,
            const float* __restrict__ bias,
            float* __restrict__ out)
{
    extern __shared__ float sm[];
    float* Ws = sm;                 // [128][128]
    float* As = sm + FF * FF;       // [128][AS_STRIDE]

    int tid  = threadIdx.x;
    int row0 = blockIdx.x * 128;

    for (int i = tid; i < FF * FF / 4; i += 256)
        ((float4*)Ws)[i] = ((const float4*)W)[i];

    for (int i = tid; i < 128 * (FF / 4); i += 256) {
        int lr = i >> 5;
        int c4 = i & 31;
        int gr = row0 + lr;
        float4 v = make_float4(0.f, 0.f, 0.f, 0.f);
        if (gr < NN) v = ((const float4*)g_pre)[(size_t)gr * 32 + c4];
        ((float4*)(As + lr * AS_STRIDE))[c4] = v;
    }
    __syncthreads();

    int rg = tid >> 4;
    int cg = tid & 15;
    int rbase = rg * 8;
    int cbase = cg * 8;

    unsigned long long acc[8][4];
#pragma unroll
    for (int i = 0; i < 8; i++)
#pragma unroll
        for (int j = 0; j < 4; j++)
            acc[i][j] = 0ull;

#pragma unroll 1
    for (int k0 = 0; k0 < FF; k0 += 4) {
        unsigned long long bb[4][4];
#pragma unroll
        for (int kk = 0; kk < 4; kk++) {
            const float* wrow = Ws + (k0 + kk) * FF + cbase;
            ulonglong2 b01 = *(const ulonglong2*)(wrow);
            ulonglong2 b23 = *(const ulonglong2*)(wrow + 4);
            bb[kk][0] = b01.x; bb[kk][1] = b01.y;
            bb[kk][2] = b23.x; bb[kk][3] = b23.y;
        }

#pragma unroll
        for (int i = 0; i < 8; i++) {
            float4 av = *(const float4*)(As + (rbase + i) * AS_STRIDE + k0);
            float a4[4] = {av.x, av.y, av.z, av.w};
#pragma unroll
            for (int kk = 0; kk < 4; kk++) {
                unsigned long long ap;
                asm("mov.b64 %0, {%1, %1};" : "=l"(ap) : "r"(__float_as_uint(a4[kk])));
                asm("fma.rn.f32x2 %0, %1, %2, %0;" : "+l"(acc[i][0]) : "l"(ap), "l"(bb[kk][0]));
                asm("fma.rn.f32x2 %0, %1, %2, %0;" : "+l"(acc[i][1]) : "l"(ap), "l"(bb[kk][1]));
                asm("fma.rn.f32x2 %0, %1, %2, %0;" : "+l"(acc[i][2]) : "l"(ap), "l"(bb[kk][2]));
                asm("fma.rn.f32x2 %0, %1, %2, %0;" : "+l"(acc[i][3]) : "l"(ap), "l"(bb[kk][3]));
            }
        }
    }

    float bv[8];
#pragma unroll
    for (int j = 0; j < 8; j++) bv[j] = bias[cbase + j];

#pragma unroll
    for (int i = 0; i < 8; i++) {
        int row = row0 + rbase + i;
        if (row >= NN) break;
        float* orow = out + (size_t)row * FF + cbase;
#pragma unroll
        for (int j = 0; j < 4; j++) {
            unsigned int lo, hi;
            asm("mov.b64 {%0, %1}, %2;" : "=r"(lo), "=r"(hi) : "l"(acc[i][j]));
            float2 v;
            v.x = __uint_as_float(lo) + bv[2 * j + 0];
            v.y = __uint_as_float(hi) + bv[2 * j + 1];
            *(float2*)(orow + 2 * j) = v;
        }
    }
}

// ---------------------------------------------------------------------------
extern "C" void kernel_launch(void* const* d_in, const int* in_sizes, int n_in,
                              void* d_out, int out_size)
{
    const float* x          = (const float*)d_in[0];
    const int*   edge_rows  = (const int*)  d_in[1];
    const int*   edge_cols  = (const int*)  d_in[2];
    const float* edge_vals  = (const float*)d_in[3];
    const int*   rel_ids    = (const int*)  d_in[4];
    const float* rel_coeffs = (const float*)d_in[5];
    const float* coeff_k    = (const float*)d_in[6];
    const float* dense_W    = (const float*)d_in[7];
    const float* dense_b    = (const float*)d_in[8];
    const float* bn_gamma   = (const float*)d_in[9];
    const float* bn_beta    = (const float*)d_in[10];
    const float* bn_mean    = (const float*)d_in[11];
    const float* bn_var     = (const float*)d_in[12];
    float*       out        = (float*)d_out;

    // 0) zero deg + ticket
    zero_deg_kernel<<<(NN + 255) / 256, 256>>>();
    // 1) BN -> g_h
    {
        int total = NN * (FF / 4);
        bn_kernel<<<(total + 255) / 256, 256>>>(x, bn_gamma, bn_beta, bn_mean, bn_var);
    }
    // 2) degree histogram
    hist_kernel<<<(EE + 255) / 256, 256>>>(edge_rows);
    // 3) exclusive scan (2 launches)
    scan_blocks_kernel<<<SCAN_BLOCKS, 256>>>();
    scan_addoff_kernel<<<(NN + 255) / 256, 256>>>();
    // 4) CSR fill (weights precomputed)
    fill_kernel<<<(EE + 255) / 256, 256>>>(edge_rows, edge_cols, edge_vals,
                                           rel_ids, rel_coeffs);
    // 5) SpMM-CSR + coeff residual (persistent, ticket-balanced)
    spmm_csr_kernel<<<448, 256>>>(coeff_k);
    // 6) Dense GEMM
    {
        int smem = (FF * FF + 128 * AS_STRIDE) * sizeof(float);
        cudaFuncSetAttribute(gemm_kernel,
                             cudaFuncAttributeMaxDynamicSharedMemorySize, smem);
        gemm_kernel<<<(NN + 127) / 128, 256, smem>>>(dense_W, dense_b, out);
    }
}

// round 14
// speedup vs baseline: 1.7112x; 1.7112x over previous
#include <cuda_runtime.h>
#include <cuda_bf16.h>
#include <cstdint>

#define NN 100000
#define EE 1600000
#define FF 128
#define RR 50
#define BN_EPS 1e-3f

// Scratch (allocation-free rule: device globals)
__device__ float g_h[(size_t)NN * FF];    // batchnormed features
__device__ float g_pre[(size_t)NN * FF];  // coeff-residual + aggregated messages
__device__ int   g_deg[NN];               // per-row edge count
__device__ int   g_rowptr[NN + 1];        // CSR row pointers
__device__ int   g_cursor[NN];            // fill cursors
__device__ int2  g_cpack[EE];             // packed (col, w_bits) per CSR slot
__device__ int   g_blocksum[64];          // scan partials
__device__ unsigned short g_wt_hi[FF * FF];  // W^T hi, [n][k] row-major bf16
__device__ unsigned short g_wt_lo[FF * FF];  // W^T lo, [n][k] row-major bf16

// ---------------------------------------------------------------------------
__device__ __forceinline__ uint32_t smem_u32(const void* p) {
    uint32_t a;
    asm("{ .reg .u64 t; cvta.to.shared.u64 t, %1; cvt.u32.u64 %0, t; }"
        : "=r"(a) : "l"(p));
    return a;
}
__device__ __forceinline__ uint32_t pack_bf2(float a, float b) {
    __nv_bfloat162 h2 = __floats2bfloat162_rn(a, b);
    uint32_t u; memcpy(&u, &h2, 4);
    return u;
}

// ---------------------------------------------------------------------------
// Kernel 1: BatchNorm (inference) into g_h; also zero g_deg.
// ---------------------------------------------------------------------------
__global__ void __launch_bounds__(256)
bn_kernel(const float* __restrict__ x,
          const float* __restrict__ gamma,
          const float* __restrict__ beta,
          const float* __restrict__ mean,
          const float* __restrict__ var)
{
    __shared__ float s_scale[FF], s_shift[FF];
    int tid = threadIdx.x;
    if (tid < FF) {
        float sc = gamma[tid] * rsqrtf(var[tid] + BN_EPS);
        s_scale[tid] = sc;
        s_shift[tid] = beta[tid] - mean[tid] * sc;
    }
    __syncthreads();

    int idx = blockIdx.x * blockDim.x + tid;
    if (idx < NN) g_deg[idx] = 0;
    if (idx >= NN * (FF / 4)) return;

    int c = (idx & 31) * 4;
    float4 xv = ((const float4*)x)[idx];
    float4 hv;
    hv.x = xv.x * s_scale[c + 0] + s_shift[c + 0];
    hv.y = xv.y * s_scale[c + 1] + s_shift[c + 1];
    hv.z = xv.z * s_scale[c + 2] + s_shift[c + 2];
    hv.w = xv.w * s_scale[c + 3] + s_shift[c + 3];
    ((float4*)g_h)[idx] = hv;
}

// ---------------------------------------------------------------------------
// Kernel W-prep: split W^T into bf16 hi/lo row-major [n][k] images.
// ---------------------------------------------------------------------------
__global__ void wprep_kernel(const float* __restrict__ W)
{
    int idx = blockIdx.x * blockDim.x + threadIdx.x;
    if (idx >= FF * FF) return;
    int n = idx >> 7, k = idx & 127;
    float v = W[k * FF + n];
    __nv_bfloat16 hb = __float2bfloat16(v);
    float lo = v - __bfloat162float(hb);
    __nv_bfloat16 lb = __float2bfloat16(lo);
    unsigned short hu, lu;
    memcpy(&hu, &hb, 2); memcpy(&lu, &lb, 2);
    g_wt_hi[idx] = hu;
    g_wt_lo[idx] = lu;
}

// ---------------------------------------------------------------------------
// Kernel 2: degree histogram
// ---------------------------------------------------------------------------
__global__ void hist_kernel(const int* __restrict__ rows)
{
    int e = blockIdx.x * blockDim.x + threadIdx.x;
    if (e < EE) atomicAdd(&g_deg[rows[e]], 1);
}

// ---------------------------------------------------------------------------
// Kernel 3a: block-local exclusive scan. 25 blocks x 256 thr x 16 elems.
// ---------------------------------------------------------------------------
#define SCB 4096
#define SCAN_BLOCKS ((NN + SCB - 1) / SCB)   // 25

__global__ void __launch_bounds__(256)
scan_blocks_kernel()
{
    __shared__ int sh[SCB];
    __shared__ int warpsums[8];
    int b = blockIdx.x, t = threadIdx.x;
    int base = b * SCB;

#pragma unroll
    for (int i = 0; i < 16; i++) {
        int idx = base + i * 256 + t;
        sh[i * 256 + t] = (idx < NN) ? g_deg[idx] : 0;
    }
    __syncthreads();

    int o = t * 16;
    int my = 0;
#pragma unroll
    for (int i = 0; i < 16; i++) my += sh[o + i];

    int lane = t & 31, wid = t >> 5;
    int pref = my;
#pragma unroll
    for (int d = 1; d < 32; d <<= 1) {
        int v = __shfl_up_sync(0xffffffffu, pref, d);
        if (lane >= d) pref += v;
    }
    if (lane == 31) warpsums[wid] = pref;
    __syncthreads();

    int woff = 0;
#pragma unroll
    for (int i = 0; i < 8; i++)
        if (i < wid) woff += warpsums[i];

    int run = woff + pref - my;
#pragma unroll
    for (int i = 0; i < 16; i++) {
        int v = sh[o + i];
        sh[o + i] = run;
        run += v;
    }
    if (t == 255) g_blocksum[b] = run;
    __syncthreads();

#pragma unroll
    for (int i = 0; i < 16; i++) {
        int idx = base + i * 256 + t;
        if (idx < NN) g_rowptr[idx] = sh[i * 256 + t];
    }
}

// ---------------------------------------------------------------------------
// Kernel 3b: add block offsets; init cursors; set rowptr[NN].
// ---------------------------------------------------------------------------
__global__ void __launch_bounds__(256)
scan_addoff_kernel()
{
    __shared__ int soff[32];
    int t = threadIdx.x;
    if (t < 32) {
        int v = (t < SCAN_BLOCKS) ? g_blocksum[t] : 0;
        int p = v;
#pragma unroll
        for (int d = 1; d < 32; d <<= 1) {
            int u = __shfl_up_sync(0xffffffffu, p, d);
            if (t >= d) p += u;
        }
        soff[t] = p - v;
    }
    __syncthreads();

    int i = blockIdx.x * blockDim.x + t;
    if (i < NN) {
        int v = g_rowptr[i] + soff[i >> 12];
        g_rowptr[i] = v;
        g_cursor[i] = v;
    }
    if (i == 0) g_rowptr[NN] = EE;
}

// ---------------------------------------------------------------------------
// Kernel 4: fill CSR slots with (col, precomputed weight)
// ---------------------------------------------------------------------------
__global__ void fill_kernel(const int*   __restrict__ rows,
                            const int*   __restrict__ cols,
                            const float* __restrict__ vals,
                            const int*   __restrict__ rels,
                            const float* __restrict__ rc)
{
    int e = blockIdx.x * blockDim.x + threadIdx.x;
    if (e >= EE) return;
    int r = rows[e];
    float w = vals[e] / (rc[rels[e]] + 1.0f);
    int pos = atomicAdd(&g_cursor[r], 1);
    int2 p;
    p.x = cols[e];
    p.y = __float_as_int(w);
    g_cpack[pos] = p;
}

// ---------------------------------------------------------------------------
// Kernel 5: SpMM-CSR (R5 config: warp/node, 8-wide unroll)
// ---------------------------------------------------------------------------
__global__ void __launch_bounds__(256)
spmm_csr_kernel(const float* __restrict__ coeff)
{
    int lane = threadIdx.x & 31;
    int node = blockIdx.x * (blockDim.x >> 5) + (threadIdx.x >> 5);
    if (node >= NN) return;

    const float4* hrow = (const float4*)(g_h + (size_t)node * FF);
    float4 hv = hrow[lane];
    float cm = coeff[node] + 1.0f;
    float ax = hv.x * cm, ay = hv.y * cm, az = hv.z * cm, aw = hv.w * cm;

    int p   = g_rowptr[node];
    int end = g_rowptr[node + 1];

    for (; p + 8 <= end; p += 8) {
        int2 e0 = g_cpack[p + 0], e1 = g_cpack[p + 1];
        int2 e2 = g_cpack[p + 2], e3 = g_cpack[p + 3];
        int2 e4 = g_cpack[p + 4], e5 = g_cpack[p + 5];
        int2 e6 = g_cpack[p + 6], e7 = g_cpack[p + 7];
        float4 h0 = __ldg(((const float4*)(g_h + (size_t)e0.x * FF)) + lane);
        float4 h1 = __ldg(((const float4*)(g_h + (size_t)e1.x * FF)) + lane);
        float4 h2 = __ldg(((const float4*)(g_h + (size_t)e2.x * FF)) + lane);
        float4 h3 = __ldg(((const float4*)(g_h + (size_t)e3.x * FF)) + lane);
        float4 h4 = __ldg(((const float4*)(g_h + (size_t)e4.x * FF)) + lane);
        float4 h5 = __ldg(((const float4*)(g_h + (size_t)e5.x * FF)) + lane);
        float4 h6 = __ldg(((const float4*)(g_h + (size_t)e6.x * FF)) + lane);
        float4 h7 = __ldg(((const float4*)(g_h + (size_t)e7.x * FF)) + lane);
        float w0 = __int_as_float(e0.y), w1 = __int_as_float(e1.y);
        float w2 = __int_as_float(e2.y), w3 = __int_as_float(e3.y);
        float w4 = __int_as_float(e4.y), w5 = __int_as_float(e5.y);
        float w6 = __int_as_float(e6.y), w7 = __int_as_float(e7.y);
        ax += w0*h0.x + w1*h1.x + w2*h2.x + w3*h3.x + w4*h4.x + w5*h5.x + w6*h6.x + w7*h7.x;
        ay += w0*h0.y + w1*h1.y + w2*h2.y + w3*h3.y + w4*h4.y + w5*h5.y + w6*h6.y + w7*h7.y;
        az += w0*h0.z + w1*h1.z + w2*h2.z + w3*h3.z + w4*h4.z + w5*h5.z + w6*h6.z + w7*h7.z;
        aw += w0*h0.w + w1*h1.w + w2*h2.w + w3*h3.w + w4*h4.w + w5*h5.w + w6*h6.w + w7*h7.w;
    }
    for (; p < end; p++) {
        int2 e0 = g_cpack[p];
        float4 h0 = __ldg(((const float4*)(g_h + (size_t)e0.x * FF)) + lane);
        float w0 = __int_as_float(e0.y);
        ax += w0 * h0.x; ay += w0 * h0.y; az += w0 * h0.z; aw += w0 * h0.w;
    }

    ((float4*)(g_pre + (size_t)node * FF))[lane] = make_float4(ax, ay, az, aw);
}

// ---------------------------------------------------------------------------
// Kernel 6: tensor-core GEMM via mma.sync m16n8k16 bf16, 2-way split:
//   D = Ahi*Bhi + Ahi*Blo + Alo*Bhi (fp32 accumulate)
// Tile 128x128x128. 8 warps in 4x2 grid; warp tile 32x64.
// SMEM rows padded to 136 bf16 (272B): conflict-free ldmatrix.
// ---------------------------------------------------------------------------
#define WT_STRIDE 136                       // bf16 units
#define ROW_BYTES (WT_STRIDE * 2)           // 272
#define SM_AHI 0
#define SM_ALO (SM_AHI + 128 * ROW_BYTES)   // 34816
#define SM_BHI (SM_ALO + 128 * ROW_BYTES)
#define SM_BLO (SM_BHI + 128 * ROW_BYTES)
#define SM_TOT (SM_BLO + 128 * ROW_BYTES)   // 139264

#define LDSM4(r0, r1, r2, r3, a) \
    asm volatile("ldmatrix.sync.aligned.m8n8.x4.shared.b16 {%0,%1,%2,%3}, [%4];" \
                 : "=r"(r0), "=r"(r1), "=r"(r2), "=r"(r3) : "r"(a))

#define MMA16816(c, a, b) \
    asm volatile("mma.sync.aligned.m16n8k16.row.col.f32.bf16.bf16.f32 " \
                 "{%0,%1,%2,%3}, {%4,%5,%6,%7}, {%8,%9}, {%0,%1,%2,%3};" \
                 : "+f"((c)[0]), "+f"((c)[1]), "+f"((c)[2]), "+f"((c)[3]) \
                 : "r"((a)[0]), "r"((a)[1]), "r"((a)[2]), "r"((a)[3]), \
                   "r"((b)[0]), "r"((b)[1]))

__global__ void __launch_bounds__(256)
gemm_mma_kernel(const float* __restrict__ bias, float* __restrict__ out)
{
    extern __shared__ char smem[];
    uint32_t sb = smem_u32(smem);
    int tid  = threadIdx.x;
    int warp = tid >> 5;
    int lane = tid & 31;
    int row0 = blockIdx.x * 128;

    // Copy W hi/lo tiles into padded SMEM (row r: 16 uint4)
    for (int i = tid; i < 128 * 16; i += 256) {
        int r = i >> 4, c = i & 15;
        *(uint4*)(smem + SM_BHI + r * ROW_BYTES + c * 16) = ((const uint4*)g_wt_hi)[i];
        *(uint4*)(smem + SM_BLO + r * ROW_BYTES + c * 16) = ((const uint4*)g_wt_lo)[i];
    }

    // Convert A (pre) tile to bf16 hi/lo: thread t -> row t>>1, k-half (t&1)*64
    {
        int lr = tid >> 1;
        int k0 = (tid & 1) * 64;
        int grow = row0 + lr;
        bool valid = (grow < NN);
        const float4* src = (const float4*)(g_pre + (size_t)grow * FF + k0);
        char* dhi = smem + SM_AHI + lr * ROW_BYTES + k0 * 2;
        char* dlo = smem + SM_ALO + lr * ROW_BYTES + k0 * 2;
#pragma unroll
        for (int j = 0; j < 16; j++) {
            float4 v = valid ? __ldg(src + j) : make_float4(0.f, 0.f, 0.f, 0.f);
            float hx = __bfloat162float(__float2bfloat16(v.x));
            float hy = __bfloat162float(__float2bfloat16(v.y));
            float hz = __bfloat162float(__float2bfloat16(v.z));
            float hw = __bfloat162float(__float2bfloat16(v.w));
            *(uint32_t*)(dhi + j * 8)     = pack_bf2(v.x, v.y);
            *(uint32_t*)(dhi + j * 8 + 4) = pack_bf2(v.z, v.w);
            *(uint32_t*)(dlo + j * 8)     = pack_bf2(v.x - hx, v.y - hy);
            *(uint32_t*)(dlo + j * 8 + 4) = pack_bf2(v.z - hz, v.w - hw);
        }
    }
    __syncthreads();

    int wm = warp >> 1;          // 0..3
    int wn = warp & 1;           // 0..1
    int arow = wm * 32;
    int bcol = wn * 64;

    float acc[2][8][4];
#pragma unroll
    for (int mt = 0; mt < 2; mt++)
#pragma unroll
        for (int nt = 0; nt < 8; nt++)
#pragma unroll
            for (int q = 0; q < 4; q++)
                acc[mt][nt][q] = 0.f;

    // A ldmatrix lane address components
    int a_r = lane & 15;          // row within 16
    int a_c = (lane >> 4) * 8;    // k-half
    // B ldmatrix lane address components
    int b_r = ((lane >> 4) << 3) + (lane & 7);  // n offset within 16
    int b_c = ((lane >> 3) & 1) * 8;            // k-half

#pragma unroll 1
    for (int ks = 0; ks < 8; ks++) {
        int kk = ks * 16;

        uint32_t ahi[2][4], alo[2][4];
#pragma unroll
        for (int mt = 0; mt < 2; mt++) {
            uint32_t off = (uint32_t)((arow + mt * 16 + a_r) * ROW_BYTES + (kk + a_c) * 2);
            LDSM4(ahi[mt][0], ahi[mt][1], ahi[mt][2], ahi[mt][3], sb + SM_AHI + off);
            LDSM4(alo[mt][0], alo[mt][1], alo[mt][2], alo[mt][3], sb + SM_ALO + off);
        }

        uint32_t bhi[8][2], blo[8][2];
#pragma unroll
        for (int g = 0; g < 4; g++) {
            uint32_t off = (uint32_t)((bcol + g * 16 + b_r) * ROW_BYTES + (kk + b_c) * 2);
            uint32_t r0, r1, r2, r3;
            LDSM4(r0, r1, r2, r3, sb + SM_BHI + off);
            bhi[g * 2 + 0][0] = r0; bhi[g * 2 + 0][1] = r1;
            bhi[g * 2 + 1][0] = r2; bhi[g * 2 + 1][1] = r3;
            LDSM4(r0, r1, r2, r3, sb + SM_BLO + off);
            blo[g * 2 + 0][0] = r0; blo[g * 2 + 0][1] = r1;
            blo[g * 2 + 1][0] = r2; blo[g * 2 + 1][1] = r3;
        }

#pragma unroll
        for (int mt = 0; mt < 2; mt++)
#pragma unroll
            for (int nt = 0; nt < 8; nt++) {
                MMA16816(acc[mt][nt], ahi[mt], bhi[nt]);
                MMA16816(acc[mt][nt], ahi[mt], blo[nt]);
                MMA16816(acc[mt][nt], alo[mt], bhi[nt]);
            }
    }

    // Epilogue: C frag (m16n8): rows lane>>2, +8; cols (lane&3)*2, +1
#pragma unroll
    for (int mt = 0; mt < 2; mt++) {
        int r_lo = row0 + arow + mt * 16 + (lane >> 2);
        int r_hi = r_lo + 8;
#pragma unroll
        for (int nt = 0; nt < 8; nt++) {
            int col = bcol + nt * 8 + (lane & 3) * 2;
            float2 bv = __ldg((const float2*)(bias + col));
            if (r_lo < NN) {
                float2 v0 = make_float2(acc[mt][nt][0] + bv.x, acc[mt][nt][1] + bv.y);
                *(float2*)(out + (size_t)r_lo * FF + col) = v0;
            }
            if (r_hi < NN) {
                float2 v1 = make_float2(acc[mt][nt][2] + bv.x, acc[mt][nt][3] + bv.y);
                *(float2*)(out + (size_t)r_hi * FF + col) = v1;
            }
        }
    }
}

// ---------------------------------------------------------------------------
extern "C" void kernel_launch(void* const* d_in, const int* in_sizes, int n_in,
                              void* d_out, int out_size)
{
    const float* x          = (const float*)d_in[0];
    const int*   edge_rows  = (const int*)  d_in[1];
    const int*   edge_cols  = (const int*)  d_in[2];
    const float* edge_vals  = (const float*)d_in[3];
    const int*   rel_ids    = (const int*)  d_in[4];
    const float* rel_coeffs = (const float*)d_in[5];
    const float* coeff_k    = (const float*)d_in[6];
    const float* dense_W    = (const float*)d_in[7];
    const float* dense_b    = (const float*)d_in[8];
    const float* bn_gamma   = (const float*)d_in[9];
    const float* bn_beta    = (const float*)d_in[10];
    const float* bn_mean    = (const float*)d_in[11];
    const float* bn_var     = (const float*)d_in[12];
    float*       out        = (float*)d_out;

    // 1) BN -> g_h, zero deg
    {
        int total = NN * (FF / 4);
        bn_kernel<<<(total + 255) / 256, 256>>>(x, bn_gamma, bn_beta, bn_mean, bn_var);
    }
    // 1b) W split prep
    wprep_kernel<<<64, 256>>>(dense_W);
    // 2) degree histogram
    hist_kernel<<<(EE + 255) / 256, 256>>>(edge_rows);
    // 3) exclusive scan (2 launches)
    scan_blocks_kernel<<<SCAN_BLOCKS, 256>>>();
    scan_addoff_kernel<<<(NN + 255) / 256, 256>>>();
    // 4) CSR fill
    fill_kernel<<<(EE + 255) / 256, 256>>>(edge_rows, edge_cols, edge_vals,
                                           rel_ids, rel_coeffs);
    // 5) SpMM-CSR + coeff residual
    spmm_csr_kernel<<<(NN + 7) / 8, 256>>>(coeff_k);
    // 6) Tensor-core GEMM (mma.sync bf16 split)
    {
        cudaFuncSetAttribute(gemm_mma_kernel,
                             cudaFuncAttributeMaxDynamicSharedMemorySize, SM_TOT);
        gemm_mma_kernel<<<(NN + 127) / 128, 256, SM_TOT>>>(dense_b, out);
    }
}